// round 16
// baseline (speedup 1.0000x reference)
#include <cuda_runtime.h>

// R15 = byte-stable resubmit (sixteenth broker timeout; kernel has never run).
// With zero verification signal, mutation of an unverified kernel has negative
// EV. Design is at the modeled fp32 issue-bound optimum: 2048 packed
// fma.f32x2/thread GEMV core, LDS/epilogue hidden in spare issue slots.
// Frozen until a bench lands.

// Problem constants
#define NQ   5
#define SDIM 32          // 2^NQ
#define QD   6
#define NG   4
#define IH   256
#define IW   256
#define OH   512
#define OW   512
#define KEEP 16
#define NW   (QD*NQ)     // 30 weights per generator
#define NPIX (OH*OW)     // 262144
#define HALF (NPIX/2)    // 131072: thread handles pixel p and p+HALF

typedef unsigned long long u64;

// Precomputed circuit matrix, k-pair packed, 2 packs per 16B slot:
// g_Mp[g][i][q] = { (M_g[4q][i], M_g[4q+1][i]) , (M_g[4q+2][i], M_g[4q+3][i]) }
// where M_g is the 6-layer variational circuit of generator g (rows k<16 kept).
__device__ ulonglong2 g_Mp[NG][SDIM][4];

__device__ __forceinline__ u64 pk(float lo, float hi) {
    u64 r;
    asm("mov.b64 %0, {%1,%2};" : "=l"(r) : "f"(lo), "f"(hi));
    return r;
}
__device__ __forceinline__ void upk(float& lo, float& hi, u64 v) {
    asm("mov.b64 {%0,%1}, %2;" : "=f"(lo), "=f"(hi) : "l"(v));
}
__device__ __forceinline__ u64 f2mul(u64 a, u64 b) {
    u64 r;
    asm("mul.rn.f32x2 %0, %1, %2;" : "=l"(r) : "l"(a), "l"(b));
    return r;
}
__device__ __forceinline__ u64 f2fma(u64 a, u64 b, u64 c) {
    u64 r;
    asm("fma.rn.f32x2 %0, %1, %2, %3;" : "=l"(r) : "l"(a), "l"(b), "l"(c));
    return r;
}

// CZ ladder sign: adjacent bit pairs (4,3),(3,2),(2,1),(1,0); negate on odd count.
// Matches reference CZ_SIGN construction exactly.
__device__ __forceinline__ bool cz_neg(int i) {
    int b4 = (i >> 4) & 1, b3 = (i >> 3) & 1, b2 = (i >> 2) & 1, b1 = (i >> 1) & 1, b0 = i & 1;
    return (((b4 & b3) + (b3 & b2) + (b2 & b1) + (b1 & b0)) & 1) != 0;
}

// ---- Prep: evolve each basis column through generator g's variational circuit.
// Thread t: g = t/32, col = t%32. Plain cos/sin gates — structurally identical
// to the reference (_ry with shared weights, then CZ, 6 layers). Runs once.
__global__ void mprep_kernel(const float* __restrict__ qp) {
    int t = threadIdx.x;
    if (t >= NG * SDIM) return;
    int g = t >> 5, col = t & 31;

    float st[SDIM];
#pragma unroll
    for (int j = 0; j < SDIM; j++) st[j] = (j == col) ? 1.0f : 0.0f;

    const float* w = qp + g * NW;
    for (int d = 0; d < QD; d++) {
        for (int q = 0; q < NQ; q++) {
            float s, c;
            sincosf(0.5f * w[d * NQ + q], &s, &c);
            int b = 4 - q;   // wire q acts on state bit (4-q)
            for (int h = 0; h < 16; h++) {
                int i0 = ((h & ~((1 << b) - 1)) << 1) | (h & ((1 << b) - 1));
                int i1 = i0 | (1 << b);
                float a0 = st[i0], a1 = st[i1];
                st[i0] = c * a0 - s * a1;
                st[i1] = s * a0 + c * a1;
            }
        }
        for (int j = 0; j < SDIM; j++)
            if (cz_neg(j)) st[j] = -st[j];
    }
    // st = column `col` of U_g; keep rows 0..15, packed as k-pairs, 2 per slot.
#pragma unroll
    for (int q2 = 0; q2 < 4; q2++)
        g_Mp[g][col][q2] = make_ulonglong2(pk(st[4*q2],   st[4*q2+1]),
                                           pk(st[4*q2+2], st[4*q2+3]));
}

// ---- Per-pixel encoding: bilinear x2 upsample (JAX half-pixel convention) then
// product-state amplitudes e[i] = prod_q (bit_{4-q}(i) ? sin(a_q/2) : cos(a_q/2)).
__device__ __forceinline__ void encode(const float* __restrict__ x, int pix,
                                       float* __restrict__ e) {
    int ox = pix & (OW - 1);
    int oy = pix >> 9;
    // coord = o/2 - 0.25: even o -> 0.25*x[i-1]+0.75*x[i]; odd -> 0.75*x[i]+0.25*x[i+1]
    // (edge clamp == JAX's in-bounds weight renormalization)
    int iy = oy >> 1, ixp = ox >> 1;
    int y0 = (oy & 1) ? iy : max(iy - 1, 0);
    int y1 = (oy & 1) ? min(iy + 1, IH - 1) : iy;
    float wy0 = (oy & 1) ? 0.75f : 0.25f;
    float wy1 = 1.0f - wy0;
    int x0 = (ox & 1) ? ixp : max(ixp - 1, 0);
    int x1 = (ox & 1) ? min(ixp + 1, IW - 1) : ixp;
    float wx0 = (ox & 1) ? 0.75f : 0.25f;
    float wx1 = 1.0f - wx0;

    const float* r00 = x + (y0 * IW + x0) * NQ;
    const float* r01 = x + (y0 * IW + x1) * NQ;
    const float* r10 = x + (y1 * IW + x0) * NQ;
    const float* r11 = x + (y1 * IW + x1) * NQ;

    float ec[NQ], es[NQ];
#pragma unroll
    for (int q = 0; q < NQ; q++) {
        float a = wy0 * (wx0 * r00[q] + wx1 * r01[q])
                + wy1 * (wx0 * r10[q] + wx1 * r11[q]);
        __sincosf(0.5f * a, &es[q], &ec[q]);
    }

    // Tensor-product tree; index i = b4 b3 b2 b1 b0, wire q <-> bit (4-q).
    float t1[2]  = {ec[0], es[0]};
    float t2[4];
#pragma unroll
    for (int i = 0; i < 2; i++) { t2[2*i] = t1[i] * ec[1]; t2[2*i+1] = t1[i] * es[1]; }
    float t3[8];
#pragma unroll
    for (int i = 0; i < 4; i++) { t3[2*i] = t2[i] * ec[2]; t3[2*i+1] = t2[i] * es[2]; }
    float t4[16];
#pragma unroll
    for (int i = 0; i < 8; i++) { t4[2*i] = t3[i] * ec[3]; t4[2*i+1] = t3[i] * es[3]; }
#pragma unroll
    for (int i = 0; i < 16; i++) { e[2*i] = t4[i] * ec[4]; e[2*i+1] = t4[i] * es[4]; }
}

// ---- Epilogue: p_k = amp_k^2, out = p / max(p).
// Reference computes (p/sum)/max(p/sum) == p/max(p): the sum cancels exactly.
// Scaling stays packed (the k-pair pack IS the output layout) and stores go out
// as 16B ulonglong2; normalizer uses MUFU.RCP (2.5e-7 rel err << 1e-3 tolerance).
__device__ __forceinline__ void emit(const u64* __restrict__ acc,
                                     float* __restrict__ optr) {
    u64 sq[8];
    float mx = 0.0f;
#pragma unroll
    for (int j = 0; j < 8; j++) {
        sq[j] = f2mul(acc[j], acc[j]);
        float lo, hi;
        upk(lo, hi, sq[j]);
        mx = fmaxf(mx, fmaxf(lo, hi));
    }
    float inv = __fdividef(1.0f, mx);
    u64 inv2 = pk(inv, inv);
    ulonglong2* o = (ulonglong2*)optr;   // 64B-aligned (pix*16 floats)
#pragma unroll
    for (int k = 0; k < 4; k++)
        o[k] = make_ulonglong2(f2mul(sq[2*k], inv2), f2mul(sq[2*k+1], inv2));
}

__global__ void __launch_bounds__(128) qmat_kernel(const float* __restrict__ x,
                                                   float* __restrict__ out) {
    __shared__ ulonglong2 Msh[NG][SDIM][4];   // 8 KB
    {   // cooperative stage of the circuit matrices (16B granules)
        const ulonglong2* gm = &g_Mp[0][0][0];
        ulonglong2* sh = &Msh[0][0][0];
        for (int k = threadIdx.x; k < NG * SDIM * 4; k += 128) sh[k] = gm[k];
    }
    __syncthreads();

    int tid = blockIdx.x * 128 + threadIdx.x;   // 0 .. HALF-1
    int pixA = tid;
    int pixB = tid + HALF;

    float eA[SDIM], eB[SDIM];
    encode(x, pixA, eA);
    encode(x, pixB, eB);

#pragma unroll 1
    for (int g = 0; g < NG; g++) {
        u64 accA[8], accB[8];
#pragma unroll
        for (int p = 0; p < 8; p++) { accA[p] = 0ULL; accB[p] = 0ULL; }

#pragma unroll
        for (int i = 0; i < SDIM; i++) {
            u64 ea2 = pk(eA[i], eA[i]);
            u64 eb2 = pk(eB[i], eB[i]);
#pragma unroll
            for (int q2 = 0; q2 < 4; q2++) {
                ulonglong2 col = Msh[g][i][q2];   // LDS.128 broadcast: 2 k-packs/issue
                accA[2*q2]   = f2fma(col.x, ea2, accA[2*q2]);
                accB[2*q2]   = f2fma(col.x, eb2, accB[2*q2]);
                accA[2*q2+1] = f2fma(col.y, ea2, accA[2*q2+1]);
                accB[2*q2+1] = f2fma(col.y, eb2, accB[2*q2+1]);
            }
        }
        float* base = out + (size_t)g * ((size_t)NPIX * KEEP);
        emit(accA, base + (size_t)pixA * KEEP);
        emit(accB, base + (size_t)pixB * KEEP);
    }
}

extern "C" void kernel_launch(void* const* d_in, const int* in_sizes, int n_in,
                              void* d_out, int out_size) {
    // Select inputs by element count (robust to metadata ordering):
    // x = 256*256*5 = 327680 elements; q_params = 4*30 = 120 elements.
    const float* x  = (const float*)d_in[0];
    const float* qp = (const float*)d_in[1];
    if (n_in >= 2 && in_sizes[0] == NG * NW && in_sizes[1] == IH * IW * NQ) {
        x  = (const float*)d_in[1];
        qp = (const float*)d_in[0];
    }
    float* out = (float*)d_out;                // [4,512,512,16] float32

    mprep_kernel<<<1, 128>>>(qp);
    qmat_kernel<<<HALF / 128, 128>>>(x, out);
}